// round 8
// baseline (speedup 1.0000x reference)
#include <cuda_runtime.h>
#include <math.h>
#include <stdint.h>

#define T_DIM 512
#define B_DIM 128
#define D_IN  128
#define H_DIM 512
#define R_DIM (T_DIM * B_DIM)

// ---- phase-2 geometry: 8 row-groups x 16 col-CTAs ----
#define GROUPS 8
#define CTAS_PER_GROUP 16
#define ROWS_PER_GROUP 16
#define COLS_PER_CTA 32

// ---- SMEM layout (floats): fragment-order A and B planes + reduce buffer ----
// A frag: [64 kt][32 lane][4 j]  = 8192 floats per plane (hi, lo)
// B frag: [64 kt][4 n][32 lane] float2 = 16384 floats per plane... (8192 float2)
#define AHI_OFF 0
#define ALO_OFF 8192
#define BHI_OFF 16384             // 8192 float2 = 16384 floats
#define BLO_OFF 32768
#define RED_OFF 49152             // red[8][16][33]
#define RED_WSTRIDE (16 * 33)     // 528
#define SMEM_FLOATS (RED_OFF + 8 * RED_WSTRIDE)   // 53376
#define RNN_SMEM_BYTES (SMEM_FLOATS * 4)          // 213504

#define FRAGA_FLOATS 8192         // per group, per plane

// ---------------- scratch (device globals: allocation-free) ----------------
__device__ __align__(16) float g_xp[(size_t)R_DIM * H_DIM];
__device__ __align__(16) float g_fragA_hi[GROUPS * FRAGA_FLOATS];
__device__ __align__(16) float g_fragA_lo[GROUPS * FRAGA_FLOATS];
__device__ int g_counts[GROUPS * 128];   // per-group counters, 512B apart

// ---------------- helpers ----------------
__device__ __forceinline__ int ld_acq(const int* p) {
    int v;
    asm volatile("ld.global.acquire.gpu.b32 %0, [%1];" : "=r"(v) : "l"(p));
    return v;
}
__device__ __forceinline__ void red_rel_add(int* p, int v) {
    asm volatile("red.release.gpu.global.add.s32 [%0], %1;" :: "l"(p), "r"(v));
}
__device__ __forceinline__ float f2tf32f(float x) {
    uint32_t r;
    asm("cvt.rna.tf32.f32 %0, %1;" : "=r"(r) : "f"(x));
    return __uint_as_float(r);
}
__device__ __forceinline__ void mma_tf32(float* d, float a0, float a1,
                                         float a2, float a3,
                                         float b0, float b1) {
    asm volatile(
        "mma.sync.aligned.m16n8k8.row.col.f32.tf32.tf32.f32 "
        "{%0,%1,%2,%3}, {%4,%5,%6,%7}, {%8,%9}, {%0,%1,%2,%3};"
        : "+f"(d[0]), "+f"(d[1]), "+f"(d[2]), "+f"(d[3])
        : "r"(__float_as_uint(a0)), "r"(__float_as_uint(a1)),
          "r"(__float_as_uint(a2)), "r"(__float_as_uint(a3)),
          "r"(__float_as_uint(b0)), "r"(__float_as_uint(b1)));
}

// ---------------- phase 1: xp = x @ W_ih^T + b_ih (unchanged) ----------------
__global__ void xp_kernel(const float* __restrict__ x,
                          const float* __restrict__ W,
                          const float* __restrict__ bias) {
    __shared__ float sA[64][68];
    __shared__ float sB[64][68];

    const int tid = threadIdx.x;
    if (blockIdx.x == 0 && blockIdx.y == 0 && tid < GROUPS) g_counts[tid * 128] = 0;

    const int tx = tid & 15;
    const int ty = tid >> 4;
    const int rbase = blockIdx.x * 64;
    const int cbase = blockIdx.y * 64;

    float acc[4][4];
#pragma unroll
    for (int i = 0; i < 4; i++)
#pragma unroll
        for (int j = 0; j < 4; j++) acc[i][j] = 0.0f;

    for (int kb = 0; kb < D_IN; kb += 64) {
#pragma unroll
        for (int i = 0; i < 4; i++) {
            int idx = i * 256 + tid;
            int row = idx >> 4;
            int k4  = idx & 15;
            float4 v = *(const float4*)&x[(size_t)(rbase + row) * D_IN + kb + k4 * 4];
            sA[k4 * 4 + 0][row] = v.x; sA[k4 * 4 + 1][row] = v.y;
            sA[k4 * 4 + 2][row] = v.z; sA[k4 * 4 + 3][row] = v.w;
            float4 w = *(const float4*)&W[(size_t)(cbase + row) * D_IN + kb + k4 * 4];
            sB[k4 * 4 + 0][row] = w.x; sB[k4 * 4 + 1][row] = w.y;
            sB[k4 * 4 + 2][row] = w.z; sB[k4 * 4 + 3][row] = w.w;
        }
        __syncthreads();
#pragma unroll
        for (int k = 0; k < 64; k++) {
            float4 a = *(const float4*)&sA[k][ty * 4];
            float4 b = *(const float4*)&sB[k][tx * 4];
            acc[0][0] = fmaf(a.x, b.x, acc[0][0]); acc[0][1] = fmaf(a.x, b.y, acc[0][1]);
            acc[0][2] = fmaf(a.x, b.z, acc[0][2]); acc[0][3] = fmaf(a.x, b.w, acc[0][3]);
            acc[1][0] = fmaf(a.y, b.x, acc[1][0]); acc[1][1] = fmaf(a.y, b.y, acc[1][1]);
            acc[1][2] = fmaf(a.y, b.z, acc[1][2]); acc[1][3] = fmaf(a.y, b.w, acc[1][3]);
            acc[2][0] = fmaf(a.z, b.x, acc[2][0]); acc[2][1] = fmaf(a.z, b.y, acc[2][1]);
            acc[2][2] = fmaf(a.z, b.z, acc[2][2]); acc[2][3] = fmaf(a.z, b.w, acc[2][3]);
            acc[3][0] = fmaf(a.w, b.x, acc[3][0]); acc[3][1] = fmaf(a.w, b.y, acc[3][1]);
            acc[3][2] = fmaf(a.w, b.z, acc[3][2]); acc[3][3] = fmaf(a.w, b.w, acc[3][3]);
        }
        __syncthreads();
    }

    float4 bj = *(const float4*)&bias[cbase + tx * 4];
#pragma unroll
    for (int i = 0; i < 4; i++) {
        float4 o;
        o.x = acc[i][0] + bj.x; o.y = acc[i][1] + bj.y;
        o.z = acc[i][2] + bj.z; o.w = acc[i][3] + bj.w;
        *(float4*)&g_xp[(size_t)(rbase + ty * 4 + i) * H_DIM + cbase + tx * 4] = o;
    }
}

// ---------------- phase 2: 3xTF32 recurrence, fragment-order exchange --------
// Producers store h's tf32 hi/lo planes directly in MMA A-fragment order to
// global scratch; consumers stage with a pure coalesced copy (no math).
// A-frag: [kt][lane][j0..3] -> 1 LDS.128/kt/plane. B-frag: [kt][n][lane]
// float2 -> 1 LDS.64 per (kt,n)/plane, built once at setup.
__global__ __launch_bounds__(256, 1)
void rnn_kernel(const float* __restrict__ Whh,
                const float* __restrict__ bhh,
                float* __restrict__ out) {
    extern __shared__ float sm[];

    const int tid  = threadIdx.x;
    const int lane = tid & 31;
    const int wrp  = tid >> 5;           // 0..7 : k-slice [64*wrp, +64)
    const int gID  = lane >> 2;          // 0..7
    const int tig  = lane & 3;           // 0..3
    const int grp  = blockIdx.x >> 4;    // 0..7
    const int cCTA = blockIdx.x & 15;    // 0..15
    const int rowbase = grp * ROWS_PER_GROUP;
    const int colbase = cCTA * COLS_PER_CTA;

    // ---- one-time: build B fragment planes from Whh ----
    // slot s = (kt*4 + n)*32 + lane : holds (W[col][k0], W[col][k0+4]) as float2
#pragma unroll
    for (int i = 0; i < 32; i++) {
        int s      = i * 256 + tid;          // 0..8191
        int lane_s = s & 31;
        int n_s    = (s >> 5) & 3;
        int kt_s   = s >> 7;
        int k0     = kt_s * 8 + (lane_s & 3);
        int cl     = n_s * 8 + (lane_s >> 2);
        float w0 = Whh[(size_t)(colbase + cl) * H_DIM + k0];
        float w1 = Whh[(size_t)(colbase + cl) * H_DIM + k0 + 4];
        float h0 = f2tf32f(w0), l0 = f2tf32f(w0 - h0);
        float h1 = f2tf32f(w1), l1 = f2tf32f(w1 - h1);
        *(float2*)&sm[BHI_OFF + s * 2] = make_float2(h0, h1);
        *(float2*)&sm[BLO_OFF + s * 2] = make_float2(l0, l1);
    }

    // epilogue mapping: o1 = (row er, col ec), o2 = (row er+8, col ec)
    const int er = tid >> 5;             // 0..7
    const int ec = tid & 31;             // 0..31
    const float biasv = bhh[colbase + ec];
    __syncthreads();

    float* const hlast = out + (size_t)T_DIM * B_DIM * H_DIM;
    int* const cnt = &g_counts[grp * 128];

    const size_t ob1 = (size_t)(rowbase + er) * H_DIM + colbase + ec;
    const size_t ob2 = (size_t)(rowbase + er + 8) * H_DIM + colbase + ec;

    // producer fragment-store coordinates (k dim of next step = this col)
    const int kc   = colbase + ec;            // 0..511
    const int kt_p = kc >> 3;
    const int ln_p = er * 4 + (kc & 3);       // lane slot (r&7 = er for both outs)
    const int j_p  = (kc & 4) ? 2 : 0;        // j for v1; v2 at j_p+1
    const size_t fbase = (size_t)grp * FRAGA_FLOATS + (size_t)(kt_p * 32 + ln_p) * 4 + j_p;

    // stage source (this group's fragment planes)
    const float4* srcH = (const float4*)(g_fragA_hi + (size_t)grp * FRAGA_FLOATS);
    const float4* srcL = (const float4*)(g_fragA_lo + (size_t)grp * FRAGA_FLOATS);

    const int ktbase = wrp * 8;

    for (int t = 0; t < T_DIM; ++t) {
        // prefetch xp early
        const float xp1 = __ldcg(&g_xp[(size_t)t * B_DIM * H_DIM + ob1]);
        const float xp2 = __ldcg(&g_xp[(size_t)t * B_DIM * H_DIM + ob2]);

        float s1 = 0.0f, s2 = 0.0f;

        if (t > 0) {
            // ---- stage: pure coalesced copy of fragment planes (no math) ----
            float4 ph[8], pl[8];
#pragma unroll
            for (int i = 0; i < 8; i++) ph[i] = __ldcg(srcH + i * 256 + tid);
#pragma unroll
            for (int i = 0; i < 8; i++) pl[i] = __ldcg(srcL + i * 256 + tid);
#pragma unroll
            for (int i = 0; i < 8; i++)
                *(float4*)&sm[AHI_OFF + (i * 256 + tid) * 4] = ph[i];
#pragma unroll
            for (int i = 0; i < 8; i++)
                *(float4*)&sm[ALO_OFF + (i * 256 + tid) * 4] = pl[i];
            __syncthreads();

            // ---- MMA: warp k-slice (8 kt), 4 n-tiles, 3 chains ----
            float accHH[4][4], accHL[4][4], accLH[4][4];
#pragma unroll
            for (int n = 0; n < 4; n++)
#pragma unroll
                for (int j = 0; j < 4; j++) {
                    accHH[n][j] = 0.0f; accHL[n][j] = 0.0f; accLH[n][j] = 0.0f;
                }

#pragma unroll
            for (int kt = 0; kt < 8; kt++) {
                const int ktg = ktbase + kt;
                float4 ah = *(const float4*)&sm[AHI_OFF + (ktg * 32 + lane) * 4];
                float4 al = *(const float4*)&sm[ALO_OFF + (ktg * 32 + lane) * 4];
#pragma unroll
                for (int n = 0; n < 4; n++) {
                    float2 bh = *(const float2*)&sm[BHI_OFF + ((ktg * 4 + n) * 32 + lane) * 2];
                    float2 bl = *(const float2*)&sm[BLO_OFF + ((ktg * 4 + n) * 32 + lane) * 2];
                    mma_tf32(accHH[n], ah.x, ah.y, ah.z, ah.w, bh.x, bh.y);
                    mma_tf32(accHL[n], ah.x, ah.y, ah.z, ah.w, bl.x, bl.y);
                    mma_tf32(accLH[n], al.x, al.y, al.z, al.w, bh.x, bh.y);
                }
            }

            // ---- write partials to red[wrp][16][33] ----
            float* rw = &sm[RED_OFF + wrp * RED_WSTRIDE];
#pragma unroll
            for (int n = 0; n < 4; n++) {
                float m0 = accHH[n][0] + accHL[n][0] + accLH[n][0];
                float m1 = accHH[n][1] + accHL[n][1] + accLH[n][1];
                float m2 = accHH[n][2] + accHL[n][2] + accLH[n][2];
                float m3 = accHH[n][3] + accHL[n][3] + accLH[n][3];
                const int c = n * 8 + 2 * tig;
                rw[gID * 33 + c]           = m0;
                rw[gID * 33 + c + 1]       = m1;
                rw[(gID + 8) * 33 + c]     = m2;
                rw[(gID + 8) * 33 + c + 1] = m3;
            }
            __syncthreads();

            // ---- reduce 8 partials for this thread's 2 outputs ----
            const int rb1 = er * 33 + ec;
            const int rb2 = (er + 8) * 33 + ec;
#pragma unroll
            for (int w = 0; w < 8; w++) {
                s1 += sm[RED_OFF + w * RED_WSTRIDE + rb1];
                s2 += sm[RED_OFF + w * RED_WSTRIDE + rb2];
            }
        }

        // ---- epilogue: tanh, output stores, fragment-plane stores ----
        float v1 = tanhf(s1 + xp1 + biasv);
        float v2 = tanhf(s2 + xp2 + biasv);
        float* hout = out + (size_t)t * B_DIM * H_DIM;
        hout[ob1] = v1;
        hout[ob2] = v2;
        if (t == T_DIM - 1) { hlast[ob1] = v1; hlast[ob2] = v2; }

        if (t < T_DIM - 1) {
            // split + store in fragment order (v1 -> j_p, v2 -> j_p+1)
            float h1 = f2tf32f(v1), l1 = f2tf32f(v1 - h1);
            float h2 = f2tf32f(v2), l2 = f2tf32f(v2 - h2);
            *(float2*)&g_fragA_hi[fbase] = make_float2(h1, h2);
            *(float2*)&g_fragA_lo[fbase] = make_float2(l1, l2);

            // per-group barrier (16 arrivals)
            __syncthreads();
            if (tid == 0) {
                red_rel_add(cnt, 1);
                const int target = CTAS_PER_GROUP * (t + 1);
                while (ld_acq(cnt) < target) { __nanosleep(16); }
            }
            __syncthreads();
        }
    }
}

// ---------------- launch ----------------
extern "C" void kernel_launch(void* const* d_in, const int* in_sizes, int n_in,
                              void* d_out, int out_size) {
    const float* x    = (const float*)d_in[0];
    const float* W_ih = (const float*)d_in[1];
    const float* b_ih = (const float*)d_in[2];
    const float* W_hh = (const float*)d_in[3];
    const float* b_hh = (const float*)d_in[4];
    float* out = (float*)d_out;

    cudaFuncSetAttribute(rnn_kernel, cudaFuncAttributeMaxDynamicSharedMemorySize,
                         RNN_SMEM_BYTES);

    xp_kernel<<<dim3(R_DIM / 64, H_DIM / 64), 256>>>(x, W_ih, b_ih);
    rnn_kernel<<<128, 256, RNN_SMEM_BYTES>>>(W_hh, b_hh, out);
}

// round 9
// speedup vs baseline: 1.2249x; 1.2249x over previous
#include <cuda_runtime.h>
#include <math.h>
#include <stdint.h>

#define T_DIM 512
#define B_DIM 128
#define D_IN  128
#define H_DIM 512
#define R_DIM (T_DIM * B_DIM)

// ---- phase-2 geometry: 8 row-groups x 16 col-CTAs ----
#define GROUPS 8
#define CTAS_PER_GROUP 16
#define ROWS_PER_GROUP 16
#define COLS_PER_CTA 32

// ---- SMEM (floats): B fragment planes + reduce buffer (A is global-direct) --
#define BHI_OFF 0                 // [64 kt][4 n][32 lane] float2 = 16384 floats
#define BLO_OFF 16384
#define RED_OFF 32768             // red[8][16][33] = 4224 floats
#define RED_WSTRIDE (16 * 33)
#define SMEM_FLOATS (RED_OFF + 8 * RED_WSTRIDE)   // 36992
#define RNN_SMEM_BYTES (SMEM_FLOATS * 4)          // 147968

#define FRAGA_FLOATS 8192         // per group, per plane, per parity

// ---------------- scratch (device globals: allocation-free) ----------------
__device__ __align__(16) float g_xp[(size_t)R_DIM * H_DIM];
__device__ __align__(16) float g_fragA_hi[2 * GROUPS * FRAGA_FLOATS];  // [par][grp][frag]
__device__ __align__(16) float g_fragA_lo[2 * GROUPS * FRAGA_FLOATS];
__device__ int g_flags[GROUPS * CTAS_PER_GROUP * 32];   // one flag per producer CTA, 128B apart

// ---------------- helpers ----------------
__device__ __forceinline__ int ld_acq(const int* p) {
    int v;
    asm volatile("ld.global.acquire.gpu.b32 %0, [%1];" : "=r"(v) : "l"(p));
    return v;
}
__device__ __forceinline__ void st_rel(int* p, int v) {
    asm volatile("st.global.release.gpu.b32 [%0], %1;" :: "l"(p), "r"(v));
}
__device__ __forceinline__ float f2tf32f(float x) {
    uint32_t r;
    asm("cvt.rna.tf32.f32 %0, %1;" : "=r"(r) : "f"(x));
    return __uint_as_float(r);
}
__device__ __forceinline__ void mma_tf32(float* d, float a0, float a1,
                                         float a2, float a3,
                                         float b0, float b1) {
    asm volatile(
        "mma.sync.aligned.m16n8k8.row.col.f32.tf32.tf32.f32 "
        "{%0,%1,%2,%3}, {%4,%5,%6,%7}, {%8,%9}, {%0,%1,%2,%3};"
        : "+f"(d[0]), "+f"(d[1]), "+f"(d[2]), "+f"(d[3])
        : "r"(__float_as_uint(a0)), "r"(__float_as_uint(a1)),
          "r"(__float_as_uint(a2)), "r"(__float_as_uint(a3)),
          "r"(__float_as_uint(b0)), "r"(__float_as_uint(b1)));
}

// ---------------- phase 1: xp = x @ W_ih^T + b_ih (unchanged) ----------------
__global__ void xp_kernel(const float* __restrict__ x,
                          const float* __restrict__ W,
                          const float* __restrict__ bias) {
    __shared__ float sA[64][68];
    __shared__ float sB[64][68];

    const int tid = threadIdx.x;
    if (blockIdx.x == 0 && blockIdx.y == 0 && tid < GROUPS * CTAS_PER_GROUP)
        g_flags[tid * 32] = 0;

    const int tx = tid & 15;
    const int ty = tid >> 4;
    const int rbase = blockIdx.x * 64;
    const int cbase = blockIdx.y * 64;

    float acc[4][4];
#pragma unroll
    for (int i = 0; i < 4; i++)
#pragma unroll
        for (int j = 0; j < 4; j++) acc[i][j] = 0.0f;

    for (int kb = 0; kb < D_IN; kb += 64) {
#pragma unroll
        for (int i = 0; i < 4; i++) {
            int idx = i * 256 + tid;
            int row = idx >> 4;
            int k4  = idx & 15;
            float4 v = *(const float4*)&x[(size_t)(rbase + row) * D_IN + kb + k4 * 4];
            sA[k4 * 4 + 0][row] = v.x; sA[k4 * 4 + 1][row] = v.y;
            sA[k4 * 4 + 2][row] = v.z; sA[k4 * 4 + 3][row] = v.w;
            float4 w = *(const float4*)&W[(size_t)(cbase + row) * D_IN + kb + k4 * 4];
            sB[k4 * 4 + 0][row] = w.x; sB[k4 * 4 + 1][row] = w.y;
            sB[k4 * 4 + 2][row] = w.z; sB[k4 * 4 + 3][row] = w.w;
        }
        __syncthreads();
#pragma unroll
        for (int k = 0; k < 64; k++) {
            float4 a = *(const float4*)&sA[k][ty * 4];
            float4 b = *(const float4*)&sB[k][tx * 4];
            acc[0][0] = fmaf(a.x, b.x, acc[0][0]); acc[0][1] = fmaf(a.x, b.y, acc[0][1]);
            acc[0][2] = fmaf(a.x, b.z, acc[0][2]); acc[0][3] = fmaf(a.x, b.w, acc[0][3]);
            acc[1][0] = fmaf(a.y, b.x, acc[1][0]); acc[1][1] = fmaf(a.y, b.y, acc[1][1]);
            acc[1][2] = fmaf(a.y, b.z, acc[1][2]); acc[1][3] = fmaf(a.y, b.w, acc[1][3]);
            acc[2][0] = fmaf(a.z, b.x, acc[2][0]); acc[2][1] = fmaf(a.z, b.y, acc[2][1]);
            acc[2][2] = fmaf(a.z, b.z, acc[2][2]); acc[2][3] = fmaf(a.z, b.w, acc[2][3]);
            acc[3][0] = fmaf(a.w, b.x, acc[3][0]); acc[3][1] = fmaf(a.w, b.y, acc[3][1]);
            acc[3][2] = fmaf(a.w, b.z, acc[3][2]); acc[3][3] = fmaf(a.w, b.w, acc[3][3]);
        }
        __syncthreads();
    }

    float4 bj = *(const float4*)&bias[cbase + tx * 4];
#pragma unroll
    for (int i = 0; i < 4; i++) {
        float4 o;
        o.x = acc[i][0] + bj.x; o.y = acc[i][1] + bj.y;
        o.z = acc[i][2] + bj.z; o.w = acc[i][3] + bj.w;
        *(float4*)&g_xp[(size_t)(rbase + ty * 4 + i) * H_DIM + cbase + tx * 4] = o;
    }
}

// ---------------- phase 2: dataflow 3xTF32 recurrence ----------------
// No group barrier. Producer CTA c sets flag[c]=t+1 (release) after storing its
// step-t frag slice (double-buffered by t&1). Consumer warp w polls ONLY its two
// producers (2w, 2w+1), front-batches 16 LDG.128 of A-frags straight from
// global, MMAs, then one CTA reduce. Output h_seq stores are off the critical
// path (after flag release).
__global__ __launch_bounds__(256, 1)
void rnn_kernel(const float* __restrict__ Whh,
                const float* __restrict__ bhh,
                float* __restrict__ out) {
    extern __shared__ float sm[];

    const int tid  = threadIdx.x;
    const int lane = tid & 31;
    const int wrp  = tid >> 5;           // 0..7 : k-slice [64*wrp, +64)
    const int gID  = lane >> 2;
    const int tig  = lane & 3;
    const int grp  = blockIdx.x >> 4;    // 0..7
    const int cCTA = blockIdx.x & 15;    // 0..15
    const int rowbase = grp * ROWS_PER_GROUP;
    const int colbase = cCTA * COLS_PER_CTA;

    // ---- one-time: build B fragment planes from Whh ----
#pragma unroll
    for (int i = 0; i < 32; i++) {
        int s      = i * 256 + tid;          // 0..8191
        int lane_s = s & 31;
        int n_s    = (s >> 5) & 3;
        int kt_s   = s >> 7;
        int k0     = kt_s * 8 + (lane_s & 3);
        int cl     = n_s * 8 + (lane_s >> 2);
        float w0 = Whh[(size_t)(colbase + cl) * H_DIM + k0];
        float w1 = Whh[(size_t)(colbase + cl) * H_DIM + k0 + 4];
        float h0 = f2tf32f(w0), l0 = f2tf32f(w0 - h0);
        float h1 = f2tf32f(w1), l1 = f2tf32f(w1 - h1);
        *(float2*)&sm[BHI_OFF + s * 2] = make_float2(h0, h1);
        *(float2*)&sm[BLO_OFF + s * 2] = make_float2(l0, l1);
    }

    const int er = tid >> 5;             // 0..7
    const int ec = tid & 31;             // 0..31
    const float biasv = bhh[colbase + ec];
    __syncthreads();

    float* const hlast = out + (size_t)T_DIM * B_DIM * H_DIM;

    const size_t ob1 = (size_t)(rowbase + er) * H_DIM + colbase + ec;
    const size_t ob2 = (size_t)(rowbase + er + 8) * H_DIM + colbase + ec;

    // producer fragment-store coordinates
    const int kc   = colbase + ec;
    const int kt_p = kc >> 3;
    const int ln_p = er * 4 + (kc & 3);
    const int j_p  = (kc & 4) ? 2 : 0;
    const size_t foff = (size_t)grp * FRAGA_FLOATS + (size_t)(kt_p * 32 + ln_p) * 4 + j_p;

    // my producer flag; consumer flags for warp's two producers
    int* const myflag = &g_flags[(grp * CTAS_PER_GROUP + cCTA) * 32];
    int* const pf0 = &g_flags[(grp * CTAS_PER_GROUP + 2 * wrp) * 32];
    int* const pf1 = &g_flags[(grp * CTAS_PER_GROUP + 2 * wrp + 1) * 32];

    const int ktbase = wrp * 8;
    const size_t grpbase = (size_t)grp * FRAGA_FLOATS;

    for (int t = 0; t < T_DIM; ++t) {
        // prefetch xp early (overlaps the flag wait)
        const float xp1 = __ldcg(&g_xp[(size_t)t * B_DIM * H_DIM + ob1]);
        const float xp2 = __ldcg(&g_xp[(size_t)t * B_DIM * H_DIM + ob2]);

        float s1 = 0.0f, s2 = 0.0f;

        if (t > 0) {
            // ---- wait for THIS warp's two producers only ----
            if (lane == 0) {
                while (ld_acq(pf0) < t) { __nanosleep(8); }
                while (ld_acq(pf1) < t) { __nanosleep(8); }
            }
            __syncwarp();

            // ---- A-frags straight from global (coalesced per kt) ----
            const int par = (t - 1) & 1;
            const float4* baseH = (const float4*)(g_fragA_hi
                                 + (size_t)par * GROUPS * FRAGA_FLOATS + grpbase);
            const float4* baseL = (const float4*)(g_fragA_lo
                                 + (size_t)par * GROUPS * FRAGA_FLOATS + grpbase);
            float4 ah[8], al[8];
#pragma unroll
            for (int kt = 0; kt < 8; kt++)
                ah[kt] = __ldcg(baseH + (ktbase + kt) * 32 + lane);
#pragma unroll
            for (int kt = 0; kt < 8; kt++)
                al[kt] = __ldcg(baseL + (ktbase + kt) * 32 + lane);

            // ---- MMA: 8 kt x 4 n x 3 chains ----
            float accHH[4][4], accHL[4][4], accLH[4][4];
#pragma unroll
            for (int n = 0; n < 4; n++)
#pragma unroll
                for (int j = 0; j < 4; j++) {
                    accHH[n][j] = 0.0f; accHL[n][j] = 0.0f; accLH[n][j] = 0.0f;
                }
#pragma unroll
            for (int kt = 0; kt < 8; kt++) {
                const int ktg = ktbase + kt;
#pragma unroll
                for (int n = 0; n < 4; n++) {
                    float2 bh = *(const float2*)&sm[BHI_OFF + ((ktg * 4 + n) * 32 + lane) * 2];
                    float2 bl = *(const float2*)&sm[BLO_OFF + ((ktg * 4 + n) * 32 + lane) * 2];
                    mma_tf32(accHH[n], ah[kt].x, ah[kt].y, ah[kt].z, ah[kt].w, bh.x, bh.y);
                    mma_tf32(accHL[n], ah[kt].x, ah[kt].y, ah[kt].z, ah[kt].w, bl.x, bl.y);
                    mma_tf32(accLH[n], al[kt].x, al[kt].y, al[kt].z, al[kt].w, bh.x, bh.y);
                }
            }

            // ---- partials to red[wrp][16][33] ----
            float* rw = &sm[RED_OFF + wrp * RED_WSTRIDE];
#pragma unroll
            for (int n = 0; n < 4; n++) {
                float m0 = accHH[n][0] + accHL[n][0] + accLH[n][0];
                float m1 = accHH[n][1] + accHL[n][1] + accLH[n][1];
                float m2 = accHH[n][2] + accHL[n][2] + accLH[n][2];
                float m3 = accHH[n][3] + accHL[n][3] + accLH[n][3];
                const int c = n * 8 + 2 * tig;
                rw[gID * 33 + c]           = m0;
                rw[gID * 33 + c + 1]       = m1;
                rw[(gID + 8) * 33 + c]     = m2;
                rw[(gID + 8) * 33 + c + 1] = m3;
            }
            __syncthreads();

            // ---- reduce 8 partials ----
            const int rb1 = er * 33 + ec;
            const int rb2 = (er + 8) * 33 + ec;
#pragma unroll
            for (int w = 0; w < 8; w++) {
                s1 += sm[RED_OFF + w * RED_WSTRIDE + rb1];
                s2 += sm[RED_OFF + w * RED_WSTRIDE + rb2];
            }
        }

        // ---- critical-path epilogue: tanh -> frag store -> flag ----
        float v1 = tanhf(s1 + xp1 + biasv);
        float v2 = tanhf(s2 + xp2 + biasv);

        if (t < T_DIM - 1) {
            const int par = t & 1;
            float h1 = f2tf32f(v1), l1 = f2tf32f(v1 - h1);
            float h2 = f2tf32f(v2), l2 = f2tf32f(v2 - h2);
            const size_t fb = (size_t)par * GROUPS * FRAGA_FLOATS + foff;
            *(float2*)&g_fragA_hi[fb] = make_float2(h1, h2);
            *(float2*)&g_fragA_lo[fb] = make_float2(l1, l2);
            __syncthreads();               // all frag stores of this CTA done
            if (tid == 0) st_rel(myflag, t + 1);
        }

        // ---- off-path: h_seq output stores ----
        float* hout = out + (size_t)t * B_DIM * H_DIM;
        hout[ob1] = v1;
        hout[ob2] = v2;
        if (t == T_DIM - 1) { hlast[ob1] = v1; hlast[ob2] = v2; }
    }
}

// ---------------- launch ----------------
extern "C" void kernel_launch(void* const* d_in, const int* in_sizes, int n_in,
                              void* d_out, int out_size) {
    const float* x    = (const float*)d_in[0];
    const float* W_ih = (const float*)d_in[1];
    const float* b_ih = (const float*)d_in[2];
    const float* W_hh = (const float*)d_in[3];
    const float* b_hh = (const float*)d_in[4];
    float* out = (float*)d_out;

    cudaFuncSetAttribute(rnn_kernel, cudaFuncAttributeMaxDynamicSharedMemorySize,
                         RNN_SMEM_BYTES);

    xp_kernel<<<dim3(R_DIM / 64, H_DIM / 64), 256>>>(x, W_ih, b_ih);
    rnn_kernel<<<128, 256, RNN_SMEM_BYTES>>>(W_hh, b_hh, out);
}

// round 11
// speedup vs baseline: 1.2774x; 1.0429x over previous
#include <cuda_runtime.h>
#include <math.h>
#include <stdint.h>

#define T_DIM 512
#define B_DIM 128
#define D_IN  128
#define H_DIM 512
#define R_DIM (T_DIM * B_DIM)

// ---- phase-2 geometry: 8 row-groups x 16 col-CTAs ----
#define GROUPS 8
#define CTAS_PER_GROUP 16
#define ROWS_PER_GROUP 16
#define COLS_PER_CTA 32

// ---- rnn SMEM (floats) ----
#define BHI_OFF 0
#define BLO_OFF 16384
#define RED_OFF 32768
#define RED_WSTRIDE (16 * 33)
#define SMEM_FLOATS (RED_OFF + 8 * RED_WSTRIDE)
#define RNN_SMEM_BYTES (SMEM_FLOATS * 4)          // 147968

#define FRAGA_FLOATS 8192

// ---- xp tensor kernel SMEM (floats): padded fragment planes ----
// A: [8 mt][16 kt] frag-rows, stride 132 (128 payload + 4 pad)
// B: [16 kt][8 n] frag-rows, stride 66 floats (32 float2 + 1 pad)
#define XAHI 0
#define XALO (8 * 16 * 132)                    // 16896
#define XBHI (2 * 8 * 16 * 132)                // 33792
#define XBLO (XBHI + 128 * 66)                 // 42240
#define XP_SMEM_FLOATS (XBLO + 128 * 66)       // 50688
#define XP_SMEM_BYTES (XP_SMEM_FLOATS * 4)     // 202752

// ---------------- scratch (device globals: allocation-free) ----------------
__device__ __align__(16) float g_xp[(size_t)R_DIM * H_DIM];
__device__ __align__(16) float g_fragA_hi[2 * GROUPS * FRAGA_FLOATS];
__device__ __align__(16) float g_fragA_lo[2 * GROUPS * FRAGA_FLOATS];
__device__ int g_flags[GROUPS * CTAS_PER_GROUP * 32];

// ---------------- helpers ----------------
__device__ __forceinline__ int ld_acq(const int* p) {
    int v;
    asm volatile("ld.global.acquire.gpu.b32 %0, [%1];" : "=r"(v) : "l"(p));
    return v;
}
__device__ __forceinline__ void st_rel(int* p, int v) {
    asm volatile("st.global.release.gpu.b32 [%0], %1;" :: "l"(p), "r"(v));
}
__device__ __forceinline__ float f2tf32f(float x) {
    uint32_t r;
    asm("cvt.rna.tf32.f32 %0, %1;" : "=r"(r) : "f"(x));
    return __uint_as_float(r);
}
__device__ __forceinline__ void mma_tf32(float* d, float a0, float a1,
                                         float a2, float a3,
                                         float b0, float b1) {
    asm volatile(
        "mma.sync.aligned.m16n8k8.row.col.f32.tf32.tf32.f32 "
        "{%0,%1,%2,%3}, {%4,%5,%6,%7}, {%8,%9}, {%0,%1,%2,%3};"
        : "+f"(d[0]), "+f"(d[1]), "+f"(d[2]), "+f"(d[3])
        : "r"(__float_as_uint(a0)), "r"(__float_as_uint(a1)),
          "r"(__float_as_uint(a2)), "r"(__float_as_uint(a3)),
          "r"(__float_as_uint(b0)), "r"(__float_as_uint(b1)));
}

// ---------------- phase 1: xp = x @ W_ih^T + b_ih  (3xTF32 tensor) ----------
// grid (512, 8), 256 threads. CTA tile M=128 x N=64, K=128 in one shot.
// Warp w: m-tiles (w>>2)*4..+3, n-pair n0=2*(w&3). 384 MMAs/warp.
__global__ __launch_bounds__(256, 1)
void xp_tf32_kernel(const float* __restrict__ x,
                    const float* __restrict__ W,
                    const float* __restrict__ bias) {
    extern __shared__ float sx[];
    const int tid  = threadIdx.x;
    const int lane = tid & 31;
    const int wrp  = tid >> 5;
    const int gID  = lane >> 2;
    const int tig  = lane & 3;
    const int rbase = blockIdx.x * 128;
    const int cbase = blockIdx.y * 64;

    if (blockIdx.x == 0 && blockIdx.y == 0 && tid < GROUPS * CTAS_PER_GROUP)
        g_flags[tid * 32] = 0;

    // ---- build A fragment planes from x tile (coalesced loads) ----
#pragma unroll
    for (int i = 0; i < 16; i++) {
        int f   = i * 256 + tid;         // 0..4095 float4 slots
        int row = f >> 5;                // 0..127
        int c4  = f & 31;                // float4 along k
        float4 v = *(const float4*)&x[(size_t)(rbase + row) * D_IN + c4 * 4];
        int mt  = row >> 4;
        int r16 = row & 15;
        int gid = r16 & 7;
        int jb  = (r16 >> 3) + 2 * (c4 & 1);   // j index for these 4 elems
        int kt  = c4 >> 1;
        int base = (mt * 16 + kt) * 132;
        float e0 = v.x, e1 = v.y, e2 = v.z, e3 = v.w;
        float h0 = f2tf32f(e0), h1 = f2tf32f(e1), h2 = f2tf32f(e2), h3 = f2tf32f(e3);
        sx[XAHI + base + (gid * 4 + 0) * 4 + jb] = h0;
        sx[XAHI + base + (gid * 4 + 1) * 4 + jb] = h1;
        sx[XAHI + base + (gid * 4 + 2) * 4 + jb] = h2;
        sx[XAHI + base + (gid * 4 + 3) * 4 + jb] = h3;
        sx[XALO + base + (gid * 4 + 0) * 4 + jb] = f2tf32f(e0 - h0);
        sx[XALO + base + (gid * 4 + 1) * 4 + jb] = f2tf32f(e1 - h1);
        sx[XALO + base + (gid * 4 + 2) * 4 + jb] = f2tf32f(e2 - h2);
        sx[XALO + base + (gid * 4 + 3) * 4 + jb] = f2tf32f(e3 - h3);
    }

    // ---- build B fragment planes from W tile ----
#pragma unroll
    for (int i = 0; i < 8; i++) {
        int f   = i * 256 + tid;         // 0..2047 float4 slots
        int row = f >> 5;                // W col 0..63
        int c4  = f & 31;
        float4 v = *(const float4*)&W[(size_t)(cbase + row) * D_IN + c4 * 4];
        int kt   = c4 >> 1;
        int n    = row >> 3;
        int lnb  = (row & 7) * 4;        // + k-offset
        int half = c4 & 1;               // 0 -> b0 slot, 1 -> b1 slot
        int base = (kt * 8 + n) * 66;
        float e0 = v.x, e1 = v.y, e2 = v.z, e3 = v.w;
        float h0 = f2tf32f(e0), h1 = f2tf32f(e1), h2 = f2tf32f(e2), h3 = f2tf32f(e3);
        sx[XBHI + base + (lnb + 0) * 2 + half] = h0;
        sx[XBHI + base + (lnb + 1) * 2 + half] = h1;
        sx[XBHI + base + (lnb + 2) * 2 + half] = h2;
        sx[XBHI + base + (lnb + 3) * 2 + half] = h3;
        sx[XBLO + base + (lnb + 0) * 2 + half] = f2tf32f(e0 - h0);
        sx[XBLO + base + (lnb + 1) * 2 + half] = f2tf32f(e1 - h1);
        sx[XBLO + base + (lnb + 2) * 2 + half] = f2tf32f(e2 - h2);
        sx[XBLO + base + (lnb + 3) * 2 + half] = f2tf32f(e3 - h3);
    }
    __syncthreads();

    // ---- MMA: warp = 4 m-tiles x 2 n-tiles, K=128 ----
    const int mh = (wrp >> 2) * 4;
    const int n0 = 2 * (wrp & 3);
    float aHH[4][2][4], aHL[4][2][4], aLH[4][2][4];
#pragma unroll
    for (int m = 0; m < 4; m++)
#pragma unroll
        for (int n = 0; n < 2; n++)
#pragma unroll
            for (int j = 0; j < 4; j++) {
                aHH[m][n][j] = 0.0f; aHL[m][n][j] = 0.0f; aLH[m][n][j] = 0.0f;
            }

#pragma unroll
    for (int kt = 0; kt < 16; kt++) {
        float2 bh[2], bl[2];
#pragma unroll
        for (int n = 0; n < 2; n++) {
            bh[n] = *(const float2*)&sx[XBHI + (kt * 8 + n0 + n) * 66 + lane * 2];
            bl[n] = *(const float2*)&sx[XBLO + (kt * 8 + n0 + n) * 66 + lane * 2];
        }
#pragma unroll
        for (int m = 0; m < 4; m++) {
            const int base = ((mh + m) * 16 + kt) * 132 + lane * 4;
            float4 ah = *(const float4*)&sx[XAHI + base];
            float4 al = *(const float4*)&sx[XALO + base];
#pragma unroll
            for (int n = 0; n < 2; n++) {
                mma_tf32(aHH[m][n], ah.x, ah.y, ah.z, ah.w, bh[n].x, bh[n].y);
                mma_tf32(aHL[m][n], ah.x, ah.y, ah.z, ah.w, bl[n].x, bl[n].y);
                mma_tf32(aLH[m][n], al.x, al.y, al.z, al.w, bh[n].x, bh[n].y);
            }
        }
    }

    // ---- epilogue: sum chains, add bias, store ----
    float bias_c[2][2];
#pragma unroll
    for (int n = 0; n < 2; n++) {
        const int col0 = cbase + (n0 + n) * 8 + 2 * tig;
        bias_c[n][0] = __ldg(&bias[col0]);
        bias_c[n][1] = __ldg(&bias[col0 + 1]);
    }
#pragma unroll
    for (int m = 0; m < 4; m++) {
        const int row0 = rbase + (mh + m) * 16 + gID;
#pragma unroll
        for (int n = 0; n < 2; n++) {
            const int col0 = cbase + (n0 + n) * 8 + 2 * tig;
            float s0 = aHH[m][n][0] + aHL[m][n][0] + aLH[m][n][0] + bias_c[n][0];
            float s1 = aHH[m][n][1] + aHL[m][n][1] + aLH[m][n][1] + bias_c[n][1];
            float s2 = aHH[m][n][2] + aHL[m][n][2] + aLH[m][n][2] + bias_c[n][0];
            float s3 = aHH[m][n][3] + aHL[m][n][3] + aLH[m][n][3] + bias_c[n][1];
            *(float2*)&g_xp[(size_t)row0 * H_DIM + col0]       = make_float2(s0, s1);
            *(float2*)&g_xp[(size_t)(row0 + 8) * H_DIM + col0] = make_float2(s2, s3);
        }
    }
}

// ---------------- phase 2: dataflow 3xTF32 recurrence (identical to R9) -----
__global__ __launch_bounds__(256, 1)
void rnn_kernel(const float* __restrict__ Whh,
                const float* __restrict__ bhh,
                float* __restrict__ out) {
    extern __shared__ float sm[];

    const int tid  = threadIdx.x;
    const int lane = tid & 31;
    const int wrp  = tid >> 5;
    const int gID  = lane >> 2;
    const int tig  = lane & 3;
    const int grp  = blockIdx.x >> 4;
    const int cCTA = blockIdx.x & 15;
    const int rowbase = grp * ROWS_PER_GROUP;
    const int colbase = cCTA * COLS_PER_CTA;

#pragma unroll
    for (int i = 0; i < 32; i++) {
        int s      = i * 256 + tid;
        int lane_s = s & 31;
        int n_s    = (s >> 5) & 3;
        int kt_s   = s >> 7;
        int k0     = kt_s * 8 + (lane_s & 3);
        int cl     = n_s * 8 + (lane_s >> 2);
        float w0 = Whh[(size_t)(colbase + cl) * H_DIM + k0];
        float w1 = Whh[(size_t)(colbase + cl) * H_DIM + k0 + 4];
        float h0 = f2tf32f(w0), l0 = f2tf32f(w0 - h0);
        float h1 = f2tf32f(w1), l1 = f2tf32f(w1 - h1);
        *(float2*)&sm[BHI_OFF + s * 2] = make_float2(h0, h1);
        *(float2*)&sm[BLO_OFF + s * 2] = make_float2(l0, l1);
    }

    const int er = tid >> 5;
    const int ec = tid & 31;
    const float biasv = bhh[colbase + ec];
    __syncthreads();

    float* const hlast = out + (size_t)T_DIM * B_DIM * H_DIM;

    const size_t ob1 = (size_t)(rowbase + er) * H_DIM + colbase + ec;
    const size_t ob2 = (size_t)(rowbase + er + 8) * H_DIM + colbase + ec;

    const int kc   = colbase + ec;
    const int kt_p = kc >> 3;
    const int ln_p = er * 4 + (kc & 3);
    const int j_p  = (kc & 4) ? 2 : 0;
    const size_t foff = (size_t)grp * FRAGA_FLOATS + (size_t)(kt_p * 32 + ln_p) * 4 + j_p;

    int* const myflag = &g_flags[(grp * CTAS_PER_GROUP + cCTA) * 32];
    int* const pf0 = &g_flags[(grp * CTAS_PER_GROUP + 2 * wrp) * 32];
    int* const pf1 = &g_flags[(grp * CTAS_PER_GROUP + 2 * wrp + 1) * 32];

    const int ktbase = wrp * 8;
    const size_t grpbase = (size_t)grp * FRAGA_FLOATS;

    for (int t = 0; t < T_DIM; ++t) {
        const float xp1 = __ldcg(&g_xp[(size_t)t * B_DIM * H_DIM + ob1]);
        const float xp2 = __ldcg(&g_xp[(size_t)t * B_DIM * H_DIM + ob2]);

        float s1 = 0.0f, s2 = 0.0f;

        if (t > 0) {
            if (lane == 0) {
                while (ld_acq(pf0) < t) { __nanosleep(8); }
                while (ld_acq(pf1) < t) { __nanosleep(8); }
            }
            __syncwarp();

            const int par = (t - 1) & 1;
            const float4* baseH = (const float4*)(g_fragA_hi
                                 + (size_t)par * GROUPS * FRAGA_FLOATS + grpbase);
            const float4* baseL = (const float4*)(g_fragA_lo
                                 + (size_t)par * GROUPS * FRAGA_FLOATS + grpbase);
            float4 ah[8], al[8];
#pragma unroll
            for (int kt = 0; kt < 8; kt++)
                ah[kt] = __ldcg(baseH + (ktbase + kt) * 32 + lane);
#pragma unroll
            for (int kt = 0; kt < 8; kt++)
                al[kt] = __ldcg(baseL + (ktbase + kt) * 32 + lane);

            float accHH[4][4], accHL[4][4], accLH[4][4];
#pragma unroll
            for (int n = 0; n < 4; n++)
#pragma unroll
                for (int j = 0; j < 4; j++) {
                    accHH[n][j] = 0.0f; accHL[n][j] = 0.0f; accLH[n][j] = 0.0f;
                }
#pragma unroll
            for (int kt = 0; kt < 8; kt++) {
                const int ktg = ktbase + kt;
#pragma unroll
                for (int n = 0; n < 4; n++) {
                    float2 bh = *(const float2*)&sm[BHI_OFF + ((ktg * 4 + n) * 32 + lane) * 2];
                    float2 bl = *(const float2*)&sm[BLO_OFF + ((ktg * 4 + n) * 32 + lane) * 2];
                    mma_tf32(accHH[n], ah[kt].x, ah[kt].y, ah[kt].z, ah[kt].w, bh.x, bh.y);
                    mma_tf32(accHL[n], ah[kt].x, ah[kt].y, ah[kt].z, ah[kt].w, bl.x, bl.y);
                    mma_tf32(accLH[n], al[kt].x, al[kt].y, al[kt].z, al[kt].w, bh.x, bh.y);
                }
            }

            float* rw = &sm[RED_OFF + wrp * RED_WSTRIDE];
#pragma unroll
            for (int n = 0; n < 4; n++) {
                float m0 = accHH[n][0] + accHL[n][0] + accLH[n][0];
                float m1 = accHH[n][1] + accHL[n][1] + accLH[n][1];
                float m2 = accHH[n][2] + accHL[n][2] + accLH[n][2];
                float m3 = accHH[n][3] + accHL[n][3] + accLH[n][3];
                const int c = n * 8 + 2 * tig;
                rw[gID * 33 + c]           = m0;
                rw[gID * 33 + c + 1]       = m1;
                rw[(gID + 8) * 33 + c]     = m2;
                rw[(gID + 8) * 33 + c + 1] = m3;
            }
            __syncthreads();

            const int rb1 = er * 33 + ec;
            const int rb2 = (er + 8) * 33 + ec;
#pragma unroll
            for (int w = 0; w < 8; w++) {
                s1 += sm[RED_OFF + w * RED_WSTRIDE + rb1];
                s2 += sm[RED_OFF + w * RED_WSTRIDE + rb2];
            }
        }

        float v1 = tanhf(s1 + xp1 + biasv);
        float v2 = tanhf(s2 + xp2 + biasv);

        if (t < T_DIM - 1) {
            const int par = t & 1;
            float h1 = f2tf32f(v1), l1 = f2tf32f(v1 - h1);
            float h2 = f2tf32f(v2), l2 = f2tf32f(v2 - h2);
            const size_t fb = (size_t)par * GROUPS * FRAGA_FLOATS + foff;
            *(float2*)&g_fragA_hi[fb] = make_float2(h1, h2);
            *(float2*)&g_fragA_lo[fb] = make_float2(l1, l2);
            __syncthreads();
            if (tid == 0) st_rel(myflag, t + 1);
        }

        float* hout = out + (size_t)t * B_DIM * H_DIM;
        hout[ob1] = v1;
        hout[ob2] = v2;
        if (t == T_DIM - 1) { hlast[ob1] = v1; hlast[ob2] = v2; }
    }
}

// ---------------- launch ----------------
extern "C" void kernel_launch(void* const* d_in, const int* in_sizes, int n_in,
                              void* d_out, int out_size) {
    const float* x    = (const float*)d_in[0];
    const float* W_ih = (const float*)d_in[1];
    const float* b_ih = (const float*)d_in[2];
    const float* W_hh = (const float*)d_in[3];
    const float* b_hh = (const float*)d_in[4];
    float* out = (float*)d_out;

    cudaFuncSetAttribute(xp_tf32_kernel, cudaFuncAttributeMaxDynamicSharedMemorySize,
                         XP_SMEM_BYTES);
    cudaFuncSetAttribute(rnn_kernel, cudaFuncAttributeMaxDynamicSharedMemorySize,
                         RNN_SMEM_BYTES);

    xp_tf32_kernel<<<dim3(R_DIM / 128, H_DIM / 64), 256, XP_SMEM_BYTES>>>(x, W_ih, b_ih);
    rnn_kernel<<<128, 256, RNN_SMEM_BYTES>>>(W_hh, b_hh, out);
}

// round 12
// speedup vs baseline: 1.4210x; 1.1124x over previous
#include <cuda_runtime.h>
#include <math.h>
#include <stdint.h>

#define T_DIM 512
#define B_DIM 128
#define D_IN  128
#define H_DIM 512

// ---- geometry: 8 row-groups x 16 col-CTAs ----
#define GROUPS 8
#define CTAS_PER_GROUP 16
#define ROWS_PER_GROUP 16
#define COLS_PER_CTA 32

// ---- SMEM layout (floats) ----
#define BHI_OFF 0                  // Whh planes: [64 kt][4 n][32 lane] float2
#define BLO_OFF 16384
#define RED_OFF 32768              // red[8][16][33]
#define RED_WSTRIDE 528
#define WIH_HI 36992               // W_ih planes: [16 kt][4 n][32 lane] float2 (4096 floats)
#define WIH_LO 41088
#define XSTG   45184               // x[t+1] stage: [16][132]
#define XPB    47296               // xp buffer: [2 parity][16][33]
#define SMEM_FLOATS 48352
#define RNN_SMEM_BYTES (SMEM_FLOATS * 4)   // 193408

#define FRAGA_FLOATS 8192

// ---------------- scratch (device globals: allocation-free) ----------------
__device__ __align__(16) float g_fragA_hi[2 * GROUPS * FRAGA_FLOATS];  // [par][grp][frag]
__device__ __align__(16) float g_fragA_lo[2 * GROUPS * FRAGA_FLOATS];
__device__ int g_flags[GROUPS * CTAS_PER_GROUP * 32];   // per-CTA flags, 128B apart (epoch-counting)

// ---------------- helpers ----------------
__device__ __forceinline__ int ld_acq(const int* p) {
    int v;
    asm volatile("ld.global.acquire.gpu.b32 %0, [%1];" : "=r"(v) : "l"(p));
    return v;
}
__device__ __forceinline__ void st_rel(int* p, int v) {
    asm volatile("st.global.release.gpu.b32 [%0], %1;" :: "l"(p), "r"(v));
}
__device__ __forceinline__ float f2tf32f(float x) {
    uint32_t r;
    asm("cvt.rna.tf32.f32 %0, %1;" : "=r"(r) : "f"(x));
    return __uint_as_float(r);
}
__device__ __forceinline__ void mma_tf32(float* d, float a0, float a1,
                                         float a2, float a3,
                                         float b0, float b1) {
    asm volatile(
        "mma.sync.aligned.m16n8k8.row.col.f32.tf32.tf32.f32 "
        "{%0,%1,%2,%3}, {%4,%5,%6,%7}, {%8,%9}, {%0,%1,%2,%3};"
        : "+f"(d[0]), "+f"(d[1]), "+f"(d[2]), "+f"(d[3])
        : "r"(__float_as_uint(a0)), "r"(__float_as_uint(a1)),
          "r"(__float_as_uint(a2)), "r"(__float_as_uint(a3)),
          "r"(__float_as_uint(b0)), "r"(__float_as_uint(b1)));
}

// ---------------- fused RNN: xp GEMM folded into recurrence idle time --------
// 128 CTAs x 256 thr, persistent. CTA = 16 batch rows x 32 hidden cols.
// Main GEMM: 8 warps k-split over Whh planes (as R11, validated).
// xp[t+1] = x[t+1] @ W_ih^T + b_ih computed by warps 0-3 AFTER the flag
// release of step t (off the inter-CTA critical path), from an SMEM-staged
// x tile, into a parity-indexed SMEM xp buffer consumed at step t+1.
// Flags count across replays: base = own flag at prologue (all equal at
// replay boundaries); wait base+t, release base+t+1. No init kernel.
__global__ __launch_bounds__(256, 1)
void rnn_fused_kernel(const float* __restrict__ x,
                      const float* __restrict__ Wih,
                      const float* __restrict__ bih,
                      const float* __restrict__ Whh,
                      const float* __restrict__ bhh,
                      float* __restrict__ out) {
    extern __shared__ float sm[];

    const int tid  = threadIdx.x;
    const int lane = tid & 31;
    const int wrp  = tid >> 5;
    const int gID  = lane >> 2;
    const int tig  = lane & 3;
    const int grp  = blockIdx.x >> 4;
    const int cCTA = blockIdx.x & 15;
    const int rowbase = grp * ROWS_PER_GROUP;
    const int colbase = cCTA * COLS_PER_CTA;

    // ---- build Whh fragment planes (validated R9/R11 layout) ----
#pragma unroll
    for (int i = 0; i < 32; i++) {
        int s      = i * 256 + tid;          // 0..8191
        int lane_s = s & 31;
        int n_s    = (s >> 5) & 3;
        int kt_s   = s >> 7;
        int k0     = kt_s * 8 + (lane_s & 3);
        int cl     = n_s * 8 + (lane_s >> 2);
        float w0 = Whh[(size_t)(colbase + cl) * H_DIM + k0];
        float w1 = Whh[(size_t)(colbase + cl) * H_DIM + k0 + 4];
        float h0 = f2tf32f(w0), l0 = f2tf32f(w0 - h0);
        float h1 = f2tf32f(w1), l1 = f2tf32f(w1 - h1);
        *(float2*)&sm[BHI_OFF + s * 2] = make_float2(h0, h1);
        *(float2*)&sm[BLO_OFF + s * 2] = make_float2(l0, l1);
    }

    // ---- build W_ih fragment planes: [16 kt][4 n][32 lane] float2 ----
#pragma unroll
    for (int i = 0; i < 8; i++) {
        int s      = i * 256 + tid;          // 0..2047
        int lane_s = s & 31;
        int n_s    = (s >> 5) & 3;
        int kt_s   = s >> 7;                 // 0..15
        int k0     = kt_s * 8 + (lane_s & 3);
        int cl     = n_s * 8 + (lane_s >> 2);
        float w0 = Wih[(size_t)(colbase + cl) * D_IN + k0];
        float w1 = Wih[(size_t)(colbase + cl) * D_IN + k0 + 4];
        float h0 = f2tf32f(w0), l0 = f2tf32f(w0 - h0);
        float h1 = f2tf32f(w1), l1 = f2tf32f(w1 - h1);
        *(float2*)&sm[WIH_HI + s * 2] = make_float2(h0, h1);
        *(float2*)&sm[WIH_LO + s * 2] = make_float2(l0, l1);
    }

    const int er = tid >> 5;
    const int ec = tid & 31;
    const float biasv = bhh[colbase + ec];
    // b_ih for xp warps (0..3): cols 8*wrp + 2*tig, +1
    float bi0 = 0.0f, bi1 = 0.0f;
    if (wrp < 4) {
        bi0 = bih[colbase + 8 * wrp + 2 * tig];
        bi1 = bih[colbase + 8 * wrp + 2 * tig + 1];
    }

    float* const hlast = out + (size_t)T_DIM * B_DIM * H_DIM;

    const size_t ob1 = (size_t)(rowbase + er) * H_DIM + colbase + ec;
    const size_t ob2 = (size_t)(rowbase + er + 8) * H_DIM + colbase + ec;

    // producer fragment-store coordinates (validated R9)
    const int kc   = colbase + ec;
    const int kt_p = kc >> 3;
    const int ln_p = er * 4 + (kc & 3);
    const int j_p  = (kc & 4) ? 2 : 0;
    const size_t foff = (size_t)grp * FRAGA_FLOATS + (size_t)(kt_p * 32 + ln_p) * 4 + j_p;

    int* const myflag = &g_flags[(grp * CTAS_PER_GROUP + cCTA) * 32];
    int* const pf0 = &g_flags[(grp * CTAS_PER_GROUP + 2 * wrp) * 32];
    int* const pf1 = &g_flags[(grp * CTAS_PER_GROUP + 2 * wrp + 1) * 32];

    const int ktbase = wrp * 8;
    const size_t grpbase = (size_t)grp * FRAGA_FLOATS;

    // epoch base: all flags carry the same value at every replay boundary
    const int base = ld_acq(myflag);

    // ---- prologue: stage x[0], compute xp[0] into parity 0 ----
    {
        int f0 = tid, f1 = tid + 256;
        int r0 = f0 >> 5, c0 = f0 & 31;
        int r1 = f1 >> 5, c1 = f1 & 31;
        float4 v0 = *(const float4*)&x[((size_t)0 * B_DIM + rowbase + r0) * D_IN + c0 * 4];
        float4 v1 = *(const float4*)&x[((size_t)0 * B_DIM + rowbase + r1) * D_IN + c1 * 4];
        *(float4*)&sm[XSTG + r0 * 132 + c0 * 4] = v0;
        *(float4*)&sm[XSTG + r1 * 132 + c1 * 4] = v1;
    }
    __syncthreads();
    if (wrp < 4) {
        float cHH[4] = {0,0,0,0}, cHL[4] = {0,0,0,0}, cLH[4] = {0,0,0,0};
#pragma unroll
        for (int kt = 0; kt < 16; kt++) {
            float a0 = sm[XSTG + gID * 132 + kt * 8 + tig];
            float a1 = sm[XSTG + (gID + 8) * 132 + kt * 8 + tig];
            float a2 = sm[XSTG + gID * 132 + kt * 8 + tig + 4];
            float a3 = sm[XSTG + (gID + 8) * 132 + kt * 8 + tig + 4];
            float ah0 = f2tf32f(a0), al0 = f2tf32f(a0 - ah0);
            float ah1 = f2tf32f(a1), al1 = f2tf32f(a1 - ah1);
            float ah2 = f2tf32f(a2), al2 = f2tf32f(a2 - ah2);
            float ah3 = f2tf32f(a3), al3 = f2tf32f(a3 - ah3);
            float2 bh = *(const float2*)&sm[WIH_HI + ((kt * 4 + wrp) * 32 + lane) * 2];
            float2 bl = *(const float2*)&sm[WIH_LO + ((kt * 4 + wrp) * 32 + lane) * 2];
            mma_tf32(cHH, ah0, ah1, ah2, ah3, bh.x, bh.y);
            mma_tf32(cHL, ah0, ah1, ah2, ah3, bl.x, bl.y);
            mma_tf32(cLH, al0, al1, al2, al3, bh.x, bh.y);
        }
        float* xb = &sm[XPB + 0 * 528];
        int c = 8 * wrp + 2 * tig;
        xb[gID * 33 + c]           = cHH[0] + cHL[0] + cLH[0] + bi0;
        xb[gID * 33 + c + 1]       = cHH[1] + cHL[1] + cLH[1] + bi1;
        xb[(gID + 8) * 33 + c]     = cHH[2] + cHL[2] + cLH[2] + bi0;
        xb[(gID + 8) * 33 + c + 1] = cHH[3] + cHL[3] + cLH[3] + bi1;
    }

    for (int t = 0; t < T_DIM; ++t) {
        // ---- early: LDG x[t+1] (DRAM latency hidden under main MMA) ----
        float4 xr0, xr1;
        int xr0r = 0, xr0c = 0, xr1r = 0, xr1c = 0;
        if (t < T_DIM - 1) {
            int f0 = tid, f1 = tid + 256;
            xr0r = f0 >> 5; xr0c = f0 & 31;
            xr1r = f1 >> 5; xr1c = f1 & 31;
            xr0 = __ldcg((const float4*)&x[((size_t)(t + 1) * B_DIM + rowbase + xr0r) * D_IN + xr0c * 4]);
            xr1 = __ldcg((const float4*)&x[((size_t)(t + 1) * B_DIM + rowbase + xr1r) * D_IN + xr1c * 4]);
        }

        if (t > 0) {
            // ---- wait for this warp's two producers ----
            if (lane == 0) {
                while (ld_acq(pf0) < base + t) { __nanosleep(8); }
                while (ld_acq(pf1) < base + t) { __nanosleep(8); }
            }
            __syncwarp();

            // ---- A-frags straight from global ----
            const int par = (t - 1) & 1;
            const float4* baseH = (const float4*)(g_fragA_hi
                                 + (size_t)par * GROUPS * FRAGA_FLOATS + grpbase);
            const float4* baseL = (const float4*)(g_fragA_lo
                                 + (size_t)par * GROUPS * FRAGA_FLOATS + grpbase);
            float4 ah[8], al[8];
#pragma unroll
            for (int kt = 0; kt < 8; kt++)
                ah[kt] = __ldcg(baseH + (ktbase + kt) * 32 + lane);
#pragma unroll
            for (int kt = 0; kt < 8; kt++)
                al[kt] = __ldcg(baseL + (ktbase + kt) * 32 + lane);

            float accHH[4][4], accHL[4][4], accLH[4][4];
#pragma unroll
            for (int n = 0; n < 4; n++)
#pragma unroll
                for (int j = 0; j < 4; j++) {
                    accHH[n][j] = 0.0f; accHL[n][j] = 0.0f; accLH[n][j] = 0.0f;
                }
#pragma unroll
            for (int kt = 0; kt < 8; kt++) {
                const int ktg = ktbase + kt;
#pragma unroll
                for (int n = 0; n < 4; n++) {
                    float2 bh = *(const float2*)&sm[BHI_OFF + ((ktg * 4 + n) * 32 + lane) * 2];
                    float2 bl = *(const float2*)&sm[BLO_OFF + ((ktg * 4 + n) * 32 + lane) * 2];
                    mma_tf32(accHH[n], ah[kt].x, ah[kt].y, ah[kt].z, ah[kt].w, bh.x, bh.y);
                    mma_tf32(accHL[n], ah[kt].x, ah[kt].y, ah[kt].z, ah[kt].w, bl.x, bl.y);
                    mma_tf32(accLH[n], al[kt].x, al[kt].y, al[kt].z, al[kt].w, bh.x, bh.y);
                }
            }

            float* rw = &sm[RED_OFF + wrp * RED_WSTRIDE];
#pragma unroll
            for (int n = 0; n < 4; n++) {
                float m0 = accHH[n][0] + accHL[n][0] + accLH[n][0];
                float m1 = accHH[n][1] + accHL[n][1] + accLH[n][1];
                float m2 = accHH[n][2] + accHL[n][2] + accLH[n][2];
                float m3 = accHH[n][3] + accHL[n][3] + accLH[n][3];
                const int c = n * 8 + 2 * tig;
                rw[gID * 33 + c]           = m0;
                rw[gID * 33 + c + 1]       = m1;
                rw[(gID + 8) * 33 + c]     = m2;
                rw[(gID + 8) * 33 + c + 1] = m3;
            }
        }
        __syncthreads();                 // SYNC1: partials ready; xpbuf[t] ready

        float s1 = 0.0f, s2 = 0.0f;
        if (t > 0) {
            const int rb1 = er * 33 + ec;
            const int rb2 = (er + 8) * 33 + ec;
#pragma unroll
            for (int w = 0; w < 8; w++) {
                s1 += sm[RED_OFF + w * RED_WSTRIDE + rb1];
                s2 += sm[RED_OFF + w * RED_WSTRIDE + rb2];
            }
        }
        const float xp1 = sm[XPB + (t & 1) * 528 + er * 33 + ec];
        const float xp2 = sm[XPB + (t & 1) * 528 + (er + 8) * 33 + ec];

        float v1 = tanhf(s1 + xp1 + biasv);
        float v2 = tanhf(s2 + xp2 + biasv);

        if (t < T_DIM - 1) {
            // frag split + store (critical path)
            const int par = t & 1;
            float h1 = f2tf32f(v1), l1 = f2tf32f(v1 - h1);
            float h2 = f2tf32f(v2), l2 = f2tf32f(v2 - h2);
            const size_t fb = (size_t)par * GROUPS * FRAGA_FLOATS + foff;
            *(float2*)&g_fragA_hi[fb] = make_float2(h1, h2);
            *(float2*)&g_fragA_lo[fb] = make_float2(l1, l2);

            // stage x[t+1] into SMEM (read by xp compute after SYNC2)
            *(float4*)&sm[XSTG + xr0r * 132 + xr0c * 4] = xr0;
            *(float4*)&sm[XSTG + xr1r * 132 + xr1c * 4] = xr1;

            __syncthreads();             // SYNC2: frag stores + xstage ready
            if (tid == 0) st_rel(myflag, base + t + 1);

            // off-critical-path: compute xp[t+1] (warps 0..3)
            if (wrp < 4) {
                float cHH[4] = {0,0,0,0}, cHL[4] = {0,0,0,0}, cLH[4] = {0,0,0,0};
#pragma unroll
                for (int kt = 0; kt < 16; kt++) {
                    float a0 = sm[XSTG + gID * 132 + kt * 8 + tig];
                    float a1 = sm[XSTG + (gID + 8) * 132 + kt * 8 + tig];
                    float a2 = sm[XSTG + gID * 132 + kt * 8 + tig + 4];
                    float a3 = sm[XSTG + (gID + 8) * 132 + kt * 8 + tig + 4];
                    float ah0 = f2tf32f(a0), al0 = f2tf32f(a0 - ah0);
                    float ah1 = f2tf32f(a1), al1 = f2tf32f(a1 - ah1);
                    float ah2 = f2tf32f(a2), al2 = f2tf32f(a2 - ah2);
                    float ah3 = f2tf32f(a3), al3 = f2tf32f(a3 - ah3);
                    float2 bh = *(const float2*)&sm[WIH_HI + ((kt * 4 + wrp) * 32 + lane) * 2];
                    float2 bl = *(const float2*)&sm[WIH_LO + ((kt * 4 + wrp) * 32 + lane) * 2];
                    mma_tf32(cHH, ah0, ah1, ah2, ah3, bh.x, bh.y);
                    mma_tf32(cHL, ah0, ah1, ah2, ah3, bl.x, bl.y);
                    mma_tf32(cLH, al0, al1, al2, al3, bh.x, bh.y);
                }
                float* xb = &sm[XPB + ((t + 1) & 1) * 528];
                int c = 8 * wrp + 2 * tig;
                xb[gID * 33 + c]           = cHH[0] + cHL[0] + cLH[0] + bi0;
                xb[gID * 33 + c + 1]       = cHH[1] + cHL[1] + cLH[1] + bi1;
                xb[(gID + 8) * 33 + c]     = cHH[2] + cHL[2] + cLH[2] + bi0;
                xb[(gID + 8) * 33 + c + 1] = cHH[3] + cHL[3] + cLH[3] + bi1;
            }
        }

        // h_seq output stores (off the inter-CTA critical path)
        float* hout = out + (size_t)t * B_DIM * H_DIM;
        hout[ob1] = v1;
        hout[ob2] = v2;
        if (t == T_DIM - 1) { hlast[ob1] = v1; hlast[ob2] = v2; }
    }
}

// ---------------- launch ----------------
extern "C" void kernel_launch(void* const* d_in, const int* in_sizes, int n_in,
                              void* d_out, int out_size) {
    const float* x    = (const float*)d_in[0];
    const float* W_ih = (const float*)d_in[1];
    const float* b_ih = (const float*)d_in[2];
    const float* W_hh = (const float*)d_in[3];
    const float* b_hh = (const float*)d_in[4];
    float* out = (float*)d_out;

    cudaFuncSetAttribute(rnn_fused_kernel, cudaFuncAttributeMaxDynamicSharedMemorySize,
                         RNN_SMEM_BYTES);

    rnn_fused_kernel<<<128, 256, RNN_SMEM_BYTES>>>(x, W_ih, b_ih, W_hh, b_hh, out);
}

// round 13
// speedup vs baseline: 1.4317x; 1.0075x over previous
#include <cuda_runtime.h>
#include <math.h>
#include <stdint.h>

#define T_DIM 512
#define B_DIM 128
#define D_IN  128
#define H_DIM 512

// ---- geometry: 8 row-groups x 16 col-CTAs, 512 threads / 16 warps ----
#define GROUPS 8
#define CTAS_PER_GROUP 16
#define ROWS_PER_GROUP 16
#define COLS_PER_CTA 32
#define THREADS 512

// ---- SMEM layout (floats) ----
#define BHI_OFF 0                  // Whh planes: [64 kt][4 n][32 lane] float2
#define BLO_OFF 16384
#define RED_OFF 32768              // red[16][16][33] = 8448
#define RED_WSTRIDE 528
#define WIH_HI 41216               // W_ih planes: [16 kt][4 n][32 lane] float2
#define WIH_LO 45312
#define XSTG   49408               // x[t+1] stage: [16][132] = 2112
#define XPB    51520               // xp partials: [2 khalf][2 parity][528] = 2112
#define SMEM_FLOATS 53632
#define RNN_SMEM_BYTES (SMEM_FLOATS * 4)   // 214528

#define FRAGA_FLOATS 8192

// ---------------- scratch (device globals: allocation-free) ----------------
__device__ __align__(16) float g_fragA_hi[2 * GROUPS * FRAGA_FLOATS];  // [par][grp][frag]
__device__ __align__(16) float g_fragA_lo[2 * GROUPS * FRAGA_FLOATS];
__device__ int g_flags[GROUPS * CTAS_PER_GROUP * 32];   // per-CTA epoch flags, 128B apart

// ---------------- helpers ----------------
__device__ __forceinline__ int ld_acq(const int* p) {
    int v;
    asm volatile("ld.global.acquire.gpu.b32 %0, [%1];" : "=r"(v) : "l"(p));
    return v;
}
__device__ __forceinline__ void st_rel(int* p, int v) {
    asm volatile("st.global.release.gpu.b32 [%0], %1;" :: "l"(p), "r"(v));
}
__device__ __forceinline__ float f2tf32f(float x) {
    uint32_t r;
    asm("cvt.rna.tf32.f32 %0, %1;" : "=r"(r) : "f"(x));
    return __uint_as_float(r);
}
__device__ __forceinline__ void mma_tf32(float* d, float a0, float a1,
                                         float a2, float a3,
                                         float b0, float b1) {
    asm volatile(
        "mma.sync.aligned.m16n8k8.row.col.f32.tf32.tf32.f32 "
        "{%0,%1,%2,%3}, {%4,%5,%6,%7}, {%8,%9}, {%0,%1,%2,%3};"
        : "+f"(d[0]), "+f"(d[1]), "+f"(d[2]), "+f"(d[3])
        : "r"(__float_as_uint(a0)), "r"(__float_as_uint(a1)),
          "r"(__float_as_uint(a2)), "r"(__float_as_uint(a3)),
          "r"(__float_as_uint(b0)), "r"(__float_as_uint(b1)));
}

// ---------------- fused RNN, 16-warp k-split, single-producer waits ----------
// CTA = 16 batch rows x 32 hidden cols. Warp w: kt [4w,4w+4) -> producer CTA w.
// Reduce: 16 partial slabs, 1 output/thread. xp[t+1] (off-path) split 2-way in
// k across warps 0-7; halves summed at consumption. Epoch flags, no init kernel.
__global__ __launch_bounds__(THREADS, 1)
void rnn_fused_kernel(const float* __restrict__ x,
                      const float* __restrict__ Wih,
                      const float* __restrict__ bih,
                      const float* __restrict__ Whh,
                      const float* __restrict__ bhh,
                      float* __restrict__ out) {
    extern __shared__ float sm[];

    const int tid  = threadIdx.x;
    const int lane = tid & 31;
    const int wrp  = tid >> 5;           // 0..15
    const int gID  = lane >> 2;
    const int tig  = lane & 3;
    const int grp  = blockIdx.x >> 4;
    const int cCTA = blockIdx.x & 15;
    const int rowbase = grp * ROWS_PER_GROUP;
    const int colbase = cCTA * COLS_PER_CTA;

    // ---- build Whh fragment planes: [64 kt][4 n][32 lane] float2 ----
#pragma unroll
    for (int i = 0; i < 16; i++) {
        int s      = i * 512 + tid;          // 0..8191
        int lane_s = s & 31;
        int n_s    = (s >> 5) & 3;
        int kt_s   = s >> 7;
        int k0     = kt_s * 8 + (lane_s & 3);
        int cl     = n_s * 8 + (lane_s >> 2);
        float w0 = Whh[(size_t)(colbase + cl) * H_DIM + k0];
        float w1 = Whh[(size_t)(colbase + cl) * H_DIM + k0 + 4];
        float h0 = f2tf32f(w0), l0 = f2tf32f(w0 - h0);
        float h1 = f2tf32f(w1), l1 = f2tf32f(w1 - h1);
        *(float2*)&sm[BHI_OFF + s * 2] = make_float2(h0, h1);
        *(float2*)&sm[BLO_OFF + s * 2] = make_float2(l0, l1);
    }
    // ---- build W_ih fragment planes: [16 kt][4 n][32 lane] float2 ----
#pragma unroll
    for (int i = 0; i < 4; i++) {
        int s      = i * 512 + tid;          // 0..2047
        int lane_s = s & 31;
        int n_s    = (s >> 5) & 3;
        int kt_s   = s >> 7;                 // 0..15
        int k0     = kt_s * 8 + (lane_s & 3);
        int cl     = n_s * 8 + (lane_s >> 2);
        float w0 = Wih[(size_t)(colbase + cl) * D_IN + k0];
        float w1 = Wih[(size_t)(colbase + cl) * D_IN + k0 + 4];
        float h0 = f2tf32f(w0), l0 = f2tf32f(w0 - h0);
        float h1 = f2tf32f(w1), l1 = f2tf32f(w1 - h1);
        *(float2*)&sm[WIH_HI + s * 2] = make_float2(h0, h1);
        *(float2*)&sm[WIH_LO + s * 2] = make_float2(l0, l1);
    }

    // per-thread output coordinate: 1 output (row, col)
    const int orow = tid >> 5;           // 0..15
    const int ocol = tid & 31;           // 0..31
    const float bhhv = bhh[colbase + ocol];
    const float bihv = bih[colbase + ocol];

    float* const hlast = out + (size_t)T_DIM * B_DIM * H_DIM;
    const size_t ob = (size_t)(rowbase + orow) * H_DIM + colbase + ocol;

    // producer fragment-store coordinates for (orow, kc)
    const int kc   = colbase + ocol;
    const int kt_p = kc >> 3;
    const int ln_p = (orow & 7) * 4 + (kc & 3);
    const int j_p  = ((kc & 4) ? 2 : 0) + (orow >> 3);
    const size_t foff = (size_t)grp * FRAGA_FLOATS + (size_t)(kt_p * 32 + ln_p) * 4 + j_p;

    int* const myflag = &g_flags[(grp * CTAS_PER_GROUP + cCTA) * 32];
    int* const pf     = &g_flags[(grp * CTAS_PER_GROUP + wrp) * 32];  // single producer

    const int ktbase = wrp * 4;
    const size_t grpbase = (size_t)grp * FRAGA_FLOATS;

    // epoch base (all flags equal at every replay boundary)
    const int base = ld_acq(myflag);

    // xp-compute role (warps 0..7): k-half kh, n-tile nx
    const int kh = wrp >> 2;             // 0..3 -> only wrp<8 used
    const int nx = wrp & 3;

    // ---- prologue: stage x[0], compute xp[0] halves into parity 0 ----
    {
        int r = tid >> 5, c = tid & 31;
        float4 v = *(const float4*)&x[((size_t)0 * B_DIM + rowbase + r) * D_IN + c * 4];
        *(float4*)&sm[XSTG + r * 132 + c * 4] = v;
    }
    __syncthreads();
    if (wrp < 8) {
        float cHH[4] = {0,0,0,0}, cHL[4] = {0,0,0,0}, cLH[4] = {0,0,0,0};
#pragma unroll
        for (int k2 = 0; k2 < 8; k2++) {
            int kt = kh * 8 + k2;
            float a0 = sm[XSTG + gID * 132 + kt * 8 + tig];
            float a1 = sm[XSTG + (gID + 8) * 132 + kt * 8 + tig];
            float a2 = sm[XSTG + gID * 132 + kt * 8 + tig + 4];
            float a3 = sm[XSTG + (gID + 8) * 132 + kt * 8 + tig + 4];
            float ah0 = f2tf32f(a0), al0 = f2tf32f(a0 - ah0);
            float ah1 = f2tf32f(a1), al1 = f2tf32f(a1 - ah1);
            float ah2 = f2tf32f(a2), al2 = f2tf32f(a2 - ah2);
            float ah3 = f2tf32f(a3), al3 = f2tf32f(a3 - ah3);
            float2 bh = *(const float2*)&sm[WIH_HI + ((kt * 4 + nx) * 32 + lane) * 2];
            float2 bl = *(const float2*)&sm[WIH_LO + ((kt * 4 + nx) * 32 + lane) * 2];
            mma_tf32(cHH, ah0, ah1, ah2, ah3, bh.x, bh.y);
            mma_tf32(cHL, ah0, ah1, ah2, ah3, bl.x, bl.y);
            mma_tf32(cLH, al0, al1, al2, al3, bh.x, bh.y);
        }
        float* xb = &sm[XPB + (kh * 2 + 0) * 528];
        int c = nx * 8 + 2 * tig;
        xb[gID * 33 + c]           = cHH[0] + cHL[0] + cLH[0];
        xb[gID * 33 + c + 1]       = cHH[1] + cHL[1] + cLH[1];
        xb[(gID + 8) * 33 + c]     = cHH[2] + cHL[2] + cLH[2];
        xb[(gID + 8) * 33 + c + 1] = cHH[3] + cHL[3] + cLH[3];
    }

    for (int t = 0; t < T_DIM; ++t) {
        // ---- early: LDG x[t+1] ----
        float4 xr;
        if (t < T_DIM - 1) {
            int r = tid >> 5, c = tid & 31;
            xr = __ldcg((const float4*)&x[((size_t)(t + 1) * B_DIM + rowbase + r) * D_IN + c * 4]);
        }

        if (t > 0) {
            // ---- wait for this warp's SINGLE producer ----
            if (lane == 0) {
                while (ld_acq(pf) < base + t) { __nanosleep(8); }
            }
            __syncwarp();

            // ---- A-frags straight from global (4 kt x 2 planes) ----
            const int par = (t - 1) & 1;
            const float4* baseH = (const float4*)(g_fragA_hi
                                 + (size_t)par * GROUPS * FRAGA_FLOATS + grpbase);
            const float4* baseL = (const float4*)(g_fragA_lo
                                 + (size_t)par * GROUPS * FRAGA_FLOATS + grpbase);
            float4 ah[4], al[4];
#pragma unroll
            for (int kt = 0; kt < 4; kt++)
                ah[kt] = __ldcg(baseH + (ktbase + kt) * 32 + lane);
#pragma unroll
            for (int kt = 0; kt < 4; kt++)
                al[kt] = __ldcg(baseL + (ktbase + kt) * 32 + lane);

            float accHH[4][4], accHL[4][4], accLH[4][4];
#pragma unroll
            for (int n = 0; n < 4; n++)
#pragma unroll
                for (int j = 0; j < 4; j++) {
                    accHH[n][j] = 0.0f; accHL[n][j] = 0.0f; accLH[n][j] = 0.0f;
                }
#pragma unroll
            for (int kt = 0; kt < 4; kt++) {
                const int ktg = ktbase + kt;
#pragma unroll
                for (int n = 0; n < 4; n++) {
                    float2 bh = *(const float2*)&sm[BHI_OFF + ((ktg * 4 + n) * 32 + lane) * 2];
                    float2 bl = *(const float2*)&sm[BLO_OFF + ((ktg * 4 + n) * 32 + lane) * 2];
                    mma_tf32(accHH[n], ah[kt].x, ah[kt].y, ah[kt].z, ah[kt].w, bh.x, bh.y);
                    mma_tf32(accHL[n], ah[kt].x, ah[kt].y, ah[kt].z, ah[kt].w, bl.x, bl.y);
                    mma_tf32(accLH[n], al[kt].x, al[kt].y, al[kt].z, al[kt].w, bh.x, bh.y);
                }
            }

            float* rw = &sm[RED_OFF + wrp * RED_WSTRIDE];
#pragma unroll
            for (int n = 0; n < 4; n++) {
                float m0 = accHH[n][0] + accHL[n][0] + accLH[n][0];
                float m1 = accHH[n][1] + accHL[n][1] + accLH[n][1];
                float m2 = accHH[n][2] + accHL[n][2] + accLH[n][2];
                float m3 = accHH[n][3] + accHL[n][3] + accLH[n][3];
                const int c = n * 8 + 2 * tig;
                rw[gID * 33 + c]           = m0;
                rw[gID * 33 + c + 1]       = m1;
                rw[(gID + 8) * 33 + c]     = m2;
                rw[(gID + 8) * 33 + c + 1] = m3;
            }
        }
        __syncthreads();                 // SYNC1

        float s = 0.0f;
        if (t > 0) {
            const int rb = orow * 33 + ocol;
#pragma unroll
            for (int u = 0; u < 16; u++)
                s += sm[RED_OFF + u * RED_WSTRIDE + rb];
        }
        const int par_x = t & 1;
        const float xpv = sm[XPB + (0 * 2 + par_x) * 528 + orow * 33 + ocol]
                        + sm[XPB + (1 * 2 + par_x) * 528 + orow * 33 + ocol];

        float v = tanhf(s + xpv + bihv + bhhv);

        if (t < T_DIM - 1) {
            // frag split + store (critical path)
            const int par = t & 1;
            float hv = f2tf32f(v), lv = f2tf32f(v - hv);
            const size_t fb = (size_t)par * GROUPS * FRAGA_FLOATS + foff;
            g_fragA_hi[fb] = hv;
            g_fragA_lo[fb] = lv;

            // stage x[t+1]
            {
                int r = tid >> 5, c = tid & 31;
                *(float4*)&sm[XSTG + r * 132 + c * 4] = xr;
            }
            __syncthreads();             // SYNC2
            if (tid == 0) st_rel(myflag, base + t + 1);

            // off-path: xp[t+1] halves (warps 0..7)
            if (wrp < 8) {
                float cHH[4] = {0,0,0,0}, cHL[4] = {0,0,0,0}, cLH[4] = {0,0,0,0};
#pragma unroll
                for (int k2 = 0; k2 < 8; k2++) {
                    int kt = kh * 8 + k2;
                    float a0 = sm[XSTG + gID * 132 + kt * 8 + tig];
                    float a1 = sm[XSTG + (gID + 8) * 132 + kt * 8 + tig];
                    float a2 = sm[XSTG + gID * 132 + kt * 8 + tig + 4];
                    float a3 = sm[XSTG + (gID + 8) * 132 + kt * 8 + tig + 4];
                    float ah0 = f2tf32f(a0), al0 = f2tf32f(a0 - ah0);
                    float ah1 = f2tf32f(a1), al1 = f2tf32f(a1 - ah1);
                    float ah2 = f2tf32f(a2), al2 = f2tf32f(a2 - ah2);
                    float ah3 = f2tf32f(a3), al3 = f2tf32f(a3 - ah3);
                    float2 bh = *(const float2*)&sm[WIH_HI + ((kt * 4 + nx) * 32 + lane) * 2];
                    float2 bl = *(const float2*)&sm[WIH_LO + ((kt * 4 + nx) * 32 + lane) * 2];
                    mma_tf32(cHH, ah0, ah1, ah2, ah3, bh.x, bh.y);
                    mma_tf32(cHL, ah0, ah1, ah2, ah3, bl.x, bl.y);
                    mma_tf32(cLH, al0, al1, al2, al3, bh.x, bh.y);
                }
                float* xb = &sm[XPB + (kh * 2 + ((t + 1) & 1)) * 528];
                int c = nx * 8 + 2 * tig;
                xb[gID * 33 + c]           = cHH[0] + cHL[0] + cLH[0];
                xb[gID * 33 + c + 1]       = cHH[1] + cHL[1] + cLH[1];
                xb[(gID + 8) * 33 + c]     = cHH[2] + cHL[2] + cLH[2];
                xb[(gID + 8) * 33 + c + 1] = cHH[3] + cHL[3] + cLH[3];
            }
        }

        // h_seq output store (off the inter-CTA critical path)
        out[(size_t)t * B_DIM * H_DIM + ob] = v;
        if (t == T_DIM - 1) hlast[ob] = v;
    }
}

// ---------------- launch ----------------
extern "C" void kernel_launch(void* const* d_in, const int* in_sizes, int n_in,
                              void* d_out, int out_size) {
    const float* x    = (const float*)d_in[0];
    const float* W_ih = (const float*)d_in[1];
    const float* b_ih = (const float*)d_in[2];
    const float* W_hh = (const float*)d_in[3];
    const float* b_hh = (const float*)d_in[4];
    float* out = (float*)d_out;

    cudaFuncSetAttribute(rnn_fused_kernel, cudaFuncAttributeMaxDynamicSharedMemorySize,
                         RNN_SMEM_BYTES);

    rnn_fused_kernel<<<128, THREADS, RNN_SMEM_BYTES>>>(x, W_ih, b_ih, W_hh, b_hh, out);
}